// round 13
// baseline (speedup 1.0000x reference)
#include <cuda_runtime.h>
#include <cuda_fp16.h>
#include <cstdint>

// Problem constants
#define S_LEN   2048
#define B_DIM   8
#define INDIM   512
#define ODIM    256
#define NROWS   16384          // B*S
#define SEG     512            // s-positions per A chunk (4 segments)
#define SUBSEG  128            // oscillator reseed granularity

typedef unsigned long long u64;

// ---- packed fp32x2 helpers (Blackwell f32x2 pipe) -------------------------
__device__ __forceinline__ u64 pack2(float lo, float hi) {
    u64 r; asm("mov.b64 %0, {%1, %2};" : "=l"(r) : "f"(lo), "f"(hi)); return r;
}
__device__ __forceinline__ float2 unpack2(u64 v) {
    float2 f; asm("mov.b64 {%0, %1}, %2;" : "=f"(f.x), "=f"(f.y) : "l"(v)); return f;
}
__device__ __forceinline__ u64 fma2(u64 a, u64 b, u64 c) {
    u64 d; asm("fma.rn.f32x2 %0, %1, %2, %3;" : "=l"(d) : "l"(a), "l"(b), "l"(c)); return d;
}
__device__ __forceinline__ u64 add2(u64 a, u64 b) {
    u64 d; asm("add.rn.f32x2 %0, %1, %2;" : "=l"(d) : "l"(a), "l"(b)); return d;
}

// Static device scratch (allocation APIs are forbidden). Total 96 MB.
__device__ float  g_C[16384 * 512];            // 32 MB: [:,0:256]=proj (LN in place), [:,256:512]=residual
__device__ __half g_A[(size_t)SEG * 65536];    // 64 MB: chunk A_T[s][j][i] = A[s0+s,i,j], fp16

// ---------------------------------------------------------------------------
// K1: C[m,n] = sum_k X[m,k]*W[n,k]; W = rows of M (n<256) then W_res.
// 128x128x8 SGEMM, 8x8 microtile, packed f32x2 inner product (j packed).
// ---------------------------------------------------------------------------
__global__ __launch_bounds__(256) void k_proj(const float* __restrict__ X,
                                              const float* __restrict__ Mw,
                                              const float* __restrict__ Wr) {
    __shared__ float As[8][128];
    __shared__ float Bs[8][128];
    const int tid  = threadIdx.x;
    const int m0   = blockIdx.x * 128;
    const int n0   = blockIdx.y * 128;
    const int lrow = tid >> 1;
    const int lcol = (tid & 1) * 4;
    const int tx   = tid & 15;
    const int ty   = tid >> 4;

    const float* xrow = X + (size_t)(m0 + lrow) * 512;
    const float* wrow;
    {
        const int n = n0 + lrow;
        wrow = (n < 256) ? (Mw + (size_t)n * 512) : (Wr + (size_t)(n - 256) * 512);
    }

    u64 acc[8][4];
#pragma unroll
    for (int i = 0; i < 8; i++)
#pragma unroll
        for (int jp = 0; jp < 4; jp++) acc[i][jp] = 0ull;

    for (int k0 = 0; k0 < 512; k0 += 8) {
        const float4 av = *(const float4*)(xrow + k0 + lcol);
        const float4 bv = *(const float4*)(wrow + k0 + lcol);
        As[lcol + 0][lrow] = av.x; As[lcol + 1][lrow] = av.y;
        As[lcol + 2][lrow] = av.z; As[lcol + 3][lrow] = av.w;
        Bs[lcol + 0][lrow] = bv.x; Bs[lcol + 1][lrow] = bv.y;
        Bs[lcol + 2][lrow] = bv.z; Bs[lcol + 3][lrow] = bv.w;
        __syncthreads();
#pragma unroll
        for (int k = 0; k < 8; k++) {
            u64 ap[8], bp[4];
            const u64* bs2 = (const u64*)&Bs[k][tx * 8];   // 4 packed j-pairs
#pragma unroll
            for (int jp = 0; jp < 4; jp++) bp[jp] = bs2[jp];
#pragma unroll
            for (int i = 0; i < 8; i++) {
                const float a = As[k][ty * 8 + i];
                ap[i] = pack2(a, a);
            }
#pragma unroll
            for (int i = 0; i < 8; i++)
#pragma unroll
                for (int jp = 0; jp < 4; jp++)
                    acc[i][jp] = fma2(ap[i], bp[jp], acc[i][jp]);
        }
        __syncthreads();
    }

#pragma unroll
    for (int i = 0; i < 8; i++) {
        u64* crow = (u64*)(g_C + (size_t)(m0 + ty * 8 + i) * 512 + n0 + tx * 8);
#pragma unroll
        for (int jp = 0; jp < 4; jp++) crow[jp] = acc[i][jp];
    }
}

// ---------------------------------------------------------------------------
// K2: LayerNorm over 256 of C[:,0:256], IN PLACE. Warp per row, 8 rows/block.
// ---------------------------------------------------------------------------
__global__ void k_ln(const float* __restrict__ sc, const float* __restrict__ bi) {
    const int row  = blockIdx.x * 8 + threadIdx.y;
    const int lane = threadIdx.x;
    float* h = g_C + (size_t)row * 512;
    float v[8];
    float s = 0.f;
#pragma unroll
    for (int k = 0; k < 8; k++) { v[k] = h[lane + 32 * k]; s += v[k]; }
#pragma unroll
    for (int o = 16; o > 0; o >>= 1) s += __shfl_xor_sync(0xffffffffu, s, o);
    const float mu = s * (1.f / 256.f);
    float q = 0.f;
#pragma unroll
    for (int k = 0; k < 8; k++) { const float d = v[k] - mu; q = fmaf(d, d, q); }
#pragma unroll
    for (int o = 16; o > 0; o >>= 1) q += __shfl_xor_sync(0xffffffffu, q, o);
    const float inv = rsqrtf(q * (1.f / 256.f) + 1e-5f);
#pragma unroll
    for (int k = 0; k < 8; k++) {
        const int c = lane + 32 * k;
        h[c] = (v[k] - mu) * inv * sc[c] + bi[c];
    }
}

// ---------------------------------------------------------------------------
// K3: fill g_A[(s-segBase)][j][i] = A[s,i,j] = sum_g P[i,j,g]*cos(2*pi*pos_s/T)
// via the exact "magic circle" oscillator (x<-x+eps*y; y<-y-eps*x,
// eps=2*sin(pi/T) => y_n = cos(n*theta) exactly in real arithmetic).
// P is folded into the amplitude (linear homogeneous recurrence), so the
// per-step dot is 3 packed adds. Seeded by exact integer phase reduction +
// cospif/sinpif. Thread=(i,j-block), blockIdx.y = subsegment.
// ---------------------------------------------------------------------------
__global__ __launch_bounds__(256) void k_genA(const float* __restrict__ P,
                                              const float* __restrict__ per,
                                              const int*   __restrict__ pos,
                                              int segBase) {
    const int i    = threadIdx.x;
    const int j    = blockIdx.x;
    const int sub  = blockIdx.y;               // 0..3
    const int s0   = segBase + sub * SUBSEG;
    const int base = (i * 256 + j) * 8;
    const int p0   = pos[s0];

    float ep[8], xo[8], yo[8];
#pragma unroll
    for (int g = 0; g < 8; g++) {
        const float pw = P[base + g];
        const int   Ti = (int)(per[base + g] + 0.5f);   // periods are exact integers
        const float Tf = (float)Ti;
        ep[g] = 2.f * sinpif(1.f / Tf);
        const int r = p0 % Ti;                           // exact phase reduction
        yo[g] = pw * cospif((float)(2 * r) / Tf);        // pw*cos(p0*theta)
        xo[g] = pw * sinpif((float)(2 * r - 1) / Tf);    // pw*sin((p0-1/2)*theta)
    }

    u64 ep2[4], nep2[4], x2[4], y2[4];
#pragma unroll
    for (int k = 0; k < 4; k++) {
        ep2[k]  = pack2(ep[2 * k], ep[2 * k + 1]);
        nep2[k] = pack2(-ep[2 * k], -ep[2 * k + 1]);
        x2[k]   = pack2(xo[2 * k], xo[2 * k + 1]);
        y2[k]   = pack2(yo[2 * k], yo[2 * k + 1]);
    }

    __half* outp = g_A + (size_t)(sub * SUBSEG) * 65536 + j * 256 + i;
#pragma unroll 2
    for (int s = 0; s < SUBSEG; s++) {
        const u64 s01 = add2(y2[0], y2[1]);
        const u64 s23 = add2(y2[2], y2[3]);
        const float2 f = unpack2(add2(s01, s23));
        *outp = __float2half_rn(f.x + f.y);
        outp += 65536;
#pragma unroll
        for (int k = 0; k < 4; k++) x2[k] = fma2(ep2[k], y2[k], x2[k]);   // old y
#pragma unroll
        for (int k = 0; k < 4; k++) y2[k] = fma2(nep2[k], x2[k], y2[k]);  // new x
    }
}

// ---------------------------------------------------------------------------
// K4: out[b,s,i] = sum_j t[b,s,j]*A[s,i,j] + residual[b,s,i].
// Block per s, 512 threads = (bh 0..1, jq 0..3, i4 0..63). Each thread: 4
// consecutive i, 4 b's, 64 j's processed as TWO independent j-streams
// (j and j+32) for structural MLP, feeding the same 8 packed accumulators.
// __launch_bounds__(512,3) caps regs so 3 blocks (48 warps) fit per SM.
// ---------------------------------------------------------------------------
__global__ __launch_bounds__(512, 3) void k_contract(float* __restrict__ out,
                                                     int segBase) {
    __shared__ u64 t2[8][256];              // (t,t) duplicated pairs
    __shared__ u64 red[3][2][4][2][64];     // [jq-1][bh][b][i-pair][i4]
    const int sl  = blockIdx.x;
    const int s   = segBase + sl;
    const int tid = threadIdx.x;
    const int i4  = tid & 63;               // quad of 4 consecutive i
    const int jq  = (tid >> 6) & 3;         // 0..3
    const int bh  = tid >> 8;               // 0..1 (batch half)

    for (int v = tid; v < 2048; v += 512) {
        const int b = v >> 8, c = v & 255;
        const float t = g_C[((size_t)b * S_LEN + s) * 512 + c];
        t2[b][c] = pack2(t, t);
    }
    __syncthreads();

    u64 acc[4][2];
#pragma unroll
    for (int b = 0; b < 4; b++) { acc[b][0] = 0ull; acc[b][1] = 0ull; }

    // A rows: 256 halves = 64 uint2 per row; this thread reads uint2 #i4.
    const int j0 = jq * 64;
    const int b0 = bh * 4;
    const uint2* AbA = (const uint2*)(g_A + (size_t)sl * 65536) + (size_t)j0 * 64 + i4;
    const uint2* AbB = AbA + 32 * 64;       // second j-stream (j0+32)

#pragma unroll 2
    for (int jj = 0; jj < 32; jj++) {
        const uint2 ra = AbA[(size_t)jj * 64];      // j = j0 + jj
        const uint2 rb = AbB[(size_t)jj * 64];      // j = j0 + 32 + jj
        const float2 fa01 = __half22float2(*(const __half2*)&ra.x);
        const float2 fa23 = __half22float2(*(const __half2*)&ra.y);
        const float2 fb01 = __half22float2(*(const __half2*)&rb.x);
        const float2 fb23 = __half22float2(*(const __half2*)&rb.y);
        const u64 a01 = pack2(fa01.x, fa01.y);
        const u64 a23 = pack2(fa23.x, fa23.y);
        const u64 b01 = pack2(fb01.x, fb01.y);
        const u64 b23 = pack2(fb23.x, fb23.y);
#pragma unroll
        for (int b = 0; b < 4; b++) {
            const u64 ta = t2[b0 + b][j0 + jj];
            const u64 tb = t2[b0 + b][j0 + 32 + jj];
            acc[b][0] = fma2(ta, a01, acc[b][0]);
            acc[b][1] = fma2(ta, a23, acc[b][1]);
            acc[b][0] = fma2(tb, b01, acc[b][0]);
            acc[b][1] = fma2(tb, b23, acc[b][1]);
        }
    }

    if (jq > 0) {
#pragma unroll
        for (int b = 0; b < 4; b++) {
            red[jq - 1][bh][b][0][i4] = acc[b][0];
            red[jq - 1][bh][b][1][i4] = acc[b][1];
        }
    }
    __syncthreads();

    if (jq == 0) {
#pragma unroll
        for (int b = 0; b < 4; b++) {
            const int bg = b0 + b;
            const u64 r0 = add2(add2(acc[b][0], red[0][bh][b][0][i4]),
                                add2(red[1][bh][b][0][i4], red[2][bh][b][0][i4]));
            const u64 r1 = add2(add2(acc[b][1], red[0][bh][b][1][i4]),
                                add2(red[1][bh][b][1][i4], red[2][bh][b][1][i4]));
            const float2 s0 = unpack2(r0), s1 = unpack2(r1);
            const float4 r = *(const float4*)&g_C[((size_t)bg * S_LEN + s) * 512 + 256 + i4 * 4];
            const float4 o = make_float4(s0.x + r.x, s0.y + r.y, s1.x + r.z, s1.y + r.w);
            *(float4*)&out[((size_t)bg * S_LEN + s) * 256 + i4 * 4] = o;
        }
    }
}

// ---------------------------------------------------------------------------
// Inputs (metadata order): x, M, P, W_res, ln_scale, ln_bias, periods, positions
// ---------------------------------------------------------------------------
extern "C" void kernel_launch(void* const* d_in, const int* in_sizes, int n_in,
                              void* d_out, int out_size) {
    const float* x   = (const float*)d_in[0];
    const float* M   = (const float*)d_in[1];
    const float* P   = (const float*)d_in[2];
    const float* Wr  = (const float*)d_in[3];
    const float* lns = (const float*)d_in[4];
    const float* lnb = (const float*)d_in[5];
    const float* per = (const float*)d_in[6];
    const int*   pos = (const int*)d_in[7];
    float* out = (float*)d_out;
    (void)in_sizes; (void)n_in; (void)out_size;

    k_proj<<<dim3(128, 4), 256>>>(x, M, Wr);
    k_ln<<<2048, dim3(32, 8)>>>(lns, lnb);

    for (int seg = 0; seg < S_LEN / SEG; seg++) {
        const int segBase = seg * SEG;
        k_genA<<<dim3(256, SEG / SUBSEG), 256>>>(P, per, pos, segBase);
        k_contract<<<SEG, 512>>>(out, segBase);
    }
}

// round 15
// speedup vs baseline: 1.1273x; 1.1273x over previous
#include <cuda_runtime.h>
#include <cuda_fp16.h>
#include <cstdint>

// Problem constants
#define S_LEN   2048
#define B_DIM   8
#define INDIM   512
#define ODIM    256
#define NROWS   16384          // B*S
#define SEG     256            // s-positions per A chunk (8 segments, 32MB chunk -> L2-resident)
#define SUBSEG  128            // oscillator reseed granularity

typedef unsigned long long u64;

// ---- packed fp32x2 helpers (Blackwell f32x2 pipe) -------------------------
__device__ __forceinline__ u64 pack2(float lo, float hi) {
    u64 r; asm("mov.b64 %0, {%1, %2};" : "=l"(r) : "f"(lo), "f"(hi)); return r;
}
__device__ __forceinline__ float2 unpack2(u64 v) {
    float2 f; asm("mov.b64 {%0, %1}, %2;" : "=f"(f.x), "=f"(f.y) : "l"(v)); return f;
}
__device__ __forceinline__ u64 fma2(u64 a, u64 b, u64 c) {
    u64 d; asm("fma.rn.f32x2 %0, %1, %2, %3;" : "=l"(d) : "l"(a), "l"(b), "l"(c)); return d;
}
__device__ __forceinline__ u64 add2(u64 a, u64 b) {
    u64 d; asm("add.rn.f32x2 %0, %1, %2;" : "=l"(d) : "l"(a), "l"(b)); return d;
}

// Static device scratch (allocation APIs are forbidden). Total 64 MB.
__device__ float  g_C[16384 * 512];            // 32 MB: [:,0:256]=proj (LN in place), [:,256:512]=residual
__device__ __half g_A[(size_t)SEG * 65536];    // 32 MB: chunk A_T[s][j][i] = A[s0+s,i,j], fp16

// ---------------------------------------------------------------------------
// K1: C[m,n] = sum_k X[m,k]*W[n,k]; W = rows of M (n<256) then W_res.
// 128x128x8 SGEMM, 8x8 microtile, packed f32x2 inner product (j packed).
// ---------------------------------------------------------------------------
__global__ __launch_bounds__(256) void k_proj(const float* __restrict__ X,
                                              const float* __restrict__ Mw,
                                              const float* __restrict__ Wr) {
    __shared__ float As[8][128];
    __shared__ float Bs[8][128];
    const int tid  = threadIdx.x;
    const int m0   = blockIdx.x * 128;
    const int n0   = blockIdx.y * 128;
    const int lrow = tid >> 1;
    const int lcol = (tid & 1) * 4;
    const int tx   = tid & 15;
    const int ty   = tid >> 4;

    const float* xrow = X + (size_t)(m0 + lrow) * 512;
    const float* wrow;
    {
        const int n = n0 + lrow;
        wrow = (n < 256) ? (Mw + (size_t)n * 512) : (Wr + (size_t)(n - 256) * 512);
    }

    u64 acc[8][4];
#pragma unroll
    for (int i = 0; i < 8; i++)
#pragma unroll
        for (int jp = 0; jp < 4; jp++) acc[i][jp] = 0ull;

    for (int k0 = 0; k0 < 512; k0 += 8) {
        const float4 av = *(const float4*)(xrow + k0 + lcol);
        const float4 bv = *(const float4*)(wrow + k0 + lcol);
        As[lcol + 0][lrow] = av.x; As[lcol + 1][lrow] = av.y;
        As[lcol + 2][lrow] = av.z; As[lcol + 3][lrow] = av.w;
        Bs[lcol + 0][lrow] = bv.x; Bs[lcol + 1][lrow] = bv.y;
        Bs[lcol + 2][lrow] = bv.z; Bs[lcol + 3][lrow] = bv.w;
        __syncthreads();
#pragma unroll
        for (int k = 0; k < 8; k++) {
            u64 ap[8], bp[4];
            const u64* bs2 = (const u64*)&Bs[k][tx * 8];   // 4 packed j-pairs
#pragma unroll
            for (int jp = 0; jp < 4; jp++) bp[jp] = bs2[jp];
#pragma unroll
            for (int i = 0; i < 8; i++) {
                const float a = As[k][ty * 8 + i];
                ap[i] = pack2(a, a);
            }
#pragma unroll
            for (int i = 0; i < 8; i++)
#pragma unroll
                for (int jp = 0; jp < 4; jp++)
                    acc[i][jp] = fma2(ap[i], bp[jp], acc[i][jp]);
        }
        __syncthreads();
    }

#pragma unroll
    for (int i = 0; i < 8; i++) {
        u64* crow = (u64*)(g_C + (size_t)(m0 + ty * 8 + i) * 512 + n0 + tx * 8);
#pragma unroll
        for (int jp = 0; jp < 4; jp++) crow[jp] = acc[i][jp];
    }
}

// ---------------------------------------------------------------------------
// K2: LayerNorm over 256 of C[:,0:256], IN PLACE. Warp per row, 8 rows/block.
// ---------------------------------------------------------------------------
__global__ void k_ln(const float* __restrict__ sc, const float* __restrict__ bi) {
    const int row  = blockIdx.x * 8 + threadIdx.y;
    const int lane = threadIdx.x;
    float* h = g_C + (size_t)row * 512;
    float v[8];
    float s = 0.f;
#pragma unroll
    for (int k = 0; k < 8; k++) { v[k] = h[lane + 32 * k]; s += v[k]; }
#pragma unroll
    for (int o = 16; o > 0; o >>= 1) s += __shfl_xor_sync(0xffffffffu, s, o);
    const float mu = s * (1.f / 256.f);
    float q = 0.f;
#pragma unroll
    for (int k = 0; k < 8; k++) { const float d = v[k] - mu; q = fmaf(d, d, q); }
#pragma unroll
    for (int o = 16; o > 0; o >>= 1) q += __shfl_xor_sync(0xffffffffu, q, o);
    const float inv = rsqrtf(q * (1.f / 256.f) + 1e-5f);
#pragma unroll
    for (int k = 0; k < 8; k++) {
        const int c = lane + 32 * k;
        h[c] = (v[k] - mu) * inv * sc[c] + bi[c];
    }
}

// ---------------------------------------------------------------------------
// K3: fill g_A[(s-segBase)][j][i] = A[s,i,j] = sum_g P[i,j,g]*cos(2*pi*pos_s/T)
// via the exact "magic circle" oscillator (x<-x+eps*y; y<-y-eps*x,
// eps=2*sin(pi/T) => y_n = cos(n*theta) exactly in real arithmetic).
// P is folded into the amplitude (linear homogeneous recurrence), so the
// per-step dot is 3 packed adds. Seeded by exact integer phase reduction +
// cospif/sinpif. Thread=(i,j-block), blockIdx.y = subsegment.
// ---------------------------------------------------------------------------
__global__ __launch_bounds__(256) void k_genA(const float* __restrict__ P,
                                              const float* __restrict__ per,
                                              const int*   __restrict__ pos,
                                              int segBase) {
    const int i    = threadIdx.x;
    const int j    = blockIdx.x;
    const int sub  = blockIdx.y;               // 0..1
    const int s0   = segBase + sub * SUBSEG;
    const int base = (i * 256 + j) * 8;
    const int p0   = pos[s0];

    float ep[8], xo[8], yo[8];
#pragma unroll
    for (int g = 0; g < 8; g++) {
        const float pw = P[base + g];
        const int   Ti = (int)(per[base + g] + 0.5f);   // periods are exact integers
        const float Tf = (float)Ti;
        ep[g] = 2.f * sinpif(1.f / Tf);
        const int r = p0 % Ti;                           // exact phase reduction
        yo[g] = pw * cospif((float)(2 * r) / Tf);        // pw*cos(p0*theta)
        xo[g] = pw * sinpif((float)(2 * r - 1) / Tf);    // pw*sin((p0-1/2)*theta)
    }

    u64 ep2[4], nep2[4], x2[4], y2[4];
#pragma unroll
    for (int k = 0; k < 4; k++) {
        ep2[k]  = pack2(ep[2 * k], ep[2 * k + 1]);
        nep2[k] = pack2(-ep[2 * k], -ep[2 * k + 1]);
        x2[k]   = pack2(xo[2 * k], xo[2 * k + 1]);
        y2[k]   = pack2(yo[2 * k], yo[2 * k + 1]);
    }

    __half* outp = g_A + (size_t)(sub * SUBSEG) * 65536 + j * 256 + i;
#pragma unroll 2
    for (int s = 0; s < SUBSEG; s++) {
        const u64 s01 = add2(y2[0], y2[1]);
        const u64 s23 = add2(y2[2], y2[3]);
        const float2 f = unpack2(add2(s01, s23));
        *outp = __float2half_rn(f.x + f.y);
        outp += 65536;
#pragma unroll
        for (int k = 0; k < 4; k++) x2[k] = fma2(ep2[k], y2[k], x2[k]);   // old y
#pragma unroll
        for (int k = 0; k < 4; k++) y2[k] = fma2(nep2[k], x2[k], y2[k]);  // new x
    }
}

// ---------------------------------------------------------------------------
// K4: out[b,s,i] = sum_j t[b,s,j]*A[s,i,j] + residual[b,s,i].
// Grid (SEG, 2): block = (s, i-half). 256 threads = (bh 0..1, jq 0..3,
// i4 0..31 within the half). Proven R10 per-thread loop: per j: 1 LDG.64 +
// 4 broadcast LDS.64 + 8 FFMA2, 8 packed accumulators, NO register cap.
// A chunk (32 MB) is L2-resident.
// ---------------------------------------------------------------------------
__global__ __launch_bounds__(256) void k_contract(float* __restrict__ out,
                                                  int segBase) {
    __shared__ u64 t2[8][256];              // (t,t) duplicated pairs (16 KB)
    __shared__ u64 red[3][2][4][2][32];     // [jq-1][bh][b][i-pair][i4] (12 KB)
    const int sl  = blockIdx.x;             // s within segment
    const int ih  = blockIdx.y;             // i-half: 0 -> i<128, 1 -> i>=128
    const int s   = segBase + sl;
    const int tid = threadIdx.x;
    const int i4  = tid & 31;               // quad of 4 consecutive i within half
    const int jq  = (tid >> 5) & 3;         // 0..3
    const int bh  = tid >> 7;               // 0..1 (batch half)

    for (int v = tid; v < 2048; v += 256) {
        const int b = v >> 8, c = v & 255;
        const float t = g_C[((size_t)b * S_LEN + s) * 512 + c];
        t2[b][c] = pack2(t, t);
    }
    __syncthreads();

    u64 acc[4][2];
#pragma unroll
    for (int b = 0; b < 4; b++) { acc[b][0] = 0ull; acc[b][1] = 0ull; }

    // A rows: 256 halves = 64 uint2 per row; this thread reads uint2 #(ih*32+i4).
    const uint2* Ab = (const uint2*)(g_A + (size_t)sl * 65536) + ih * 32 + i4;
    const int j0 = jq * 64;
    const int b0 = bh * 4;

#pragma unroll 4
    for (int j = j0; j < j0 + 64; j++) {
        const uint2 raw = Ab[(size_t)j * 64];
        const float2 f01 = __half22float2(*(const __half2*)&raw.x);
        const float2 f23 = __half22float2(*(const __half2*)&raw.y);
        const u64 a01 = pack2(f01.x, f01.y);
        const u64 a23 = pack2(f23.x, f23.y);
#pragma unroll
        for (int b = 0; b < 4; b++) {
            const u64 t = t2[b0 + b][j];
            acc[b][0] = fma2(t, a01, acc[b][0]);
            acc[b][1] = fma2(t, a23, acc[b][1]);
        }
    }

    if (jq > 0) {
#pragma unroll
        for (int b = 0; b < 4; b++) {
            red[jq - 1][bh][b][0][i4] = acc[b][0];
            red[jq - 1][bh][b][1][i4] = acc[b][1];
        }
    }
    __syncthreads();

    if (jq == 0) {
        const int ib = ih * 128 + i4 * 4;   // global i base for this thread
#pragma unroll
        for (int b = 0; b < 4; b++) {
            const int bg = b0 + b;
            const u64 r0 = add2(add2(acc[b][0], red[0][bh][b][0][i4]),
                                add2(red[1][bh][b][0][i4], red[2][bh][b][0][i4]));
            const u64 r1 = add2(add2(acc[b][1], red[0][bh][b][1][i4]),
                                add2(red[1][bh][b][1][i4], red[2][bh][b][1][i4]));
            const float2 s0 = unpack2(r0), s1 = unpack2(r1);
            const float4 r = *(const float4*)&g_C[((size_t)bg * S_LEN + s) * 512 + 256 + ib];
            const float4 o = make_float4(s0.x + r.x, s0.y + r.y, s1.x + r.z, s1.y + r.w);
            *(float4*)&out[((size_t)bg * S_LEN + s) * 256 + ib] = o;
        }
    }
}

// ---------------------------------------------------------------------------
// Inputs (metadata order): x, M, P, W_res, ln_scale, ln_bias, periods, positions
// ---------------------------------------------------------------------------
extern "C" void kernel_launch(void* const* d_in, const int* in_sizes, int n_in,
                              void* d_out, int out_size) {
    const float* x   = (const float*)d_in[0];
    const float* M   = (const float*)d_in[1];
    const float* P   = (const float*)d_in[2];
    const float* Wr  = (const float*)d_in[3];
    const float* lns = (const float*)d_in[4];
    const float* lnb = (const float*)d_in[5];
    const float* per = (const float*)d_in[6];
    const int*   pos = (const int*)d_in[7];
    float* out = (float*)d_out;
    (void)in_sizes; (void)n_in; (void)out_size;

    k_proj<<<dim3(128, 4), 256>>>(x, M, Wr);
    k_ln<<<2048, dim3(32, 8)>>>(lns, lnb);

    for (int seg = 0; seg < S_LEN / SEG; seg++) {
        const int segBase = seg * SEG;
        k_genA<<<dim3(256, SEG / SUBSEG), 256>>>(P, per, pos, segBase);
        k_contract<<<dim3(SEG, 2), 256>>>(out, segBase);
    }
}

// round 16
// speedup vs baseline: 1.2664x; 1.1234x over previous
#include <cuda_runtime.h>
#include <cuda_fp16.h>
#include <cstdint>

// Problem constants
#define S_LEN   2048
#define B_DIM   8
#define INDIM   512
#define ODIM    256
#define NROWS   16384          // B*S
#define SEG     512            // s-positions per A chunk (4 segments)
#define SUBSEG  256            // oscillator reseed granularity

typedef unsigned long long u64;

// ---- packed fp32x2 helpers (Blackwell f32x2 pipe) -------------------------
__device__ __forceinline__ u64 pack2(float lo, float hi) {
    u64 r; asm("mov.b64 %0, {%1, %2};" : "=l"(r) : "f"(lo), "f"(hi)); return r;
}
__device__ __forceinline__ float2 unpack2(u64 v) {
    float2 f; asm("mov.b64 {%0, %1}, %2;" : "=f"(f.x), "=f"(f.y) : "l"(v)); return f;
}
__device__ __forceinline__ u64 fma2(u64 a, u64 b, u64 c) {
    u64 d; asm("fma.rn.f32x2 %0, %1, %2, %3;" : "=l"(d) : "l"(a), "l"(b), "l"(c)); return d;
}
__device__ __forceinline__ u64 add2(u64 a, u64 b) {
    u64 d; asm("add.rn.f32x2 %0, %1, %2;" : "=l"(d) : "l"(a), "l"(b)); return d;
}

// Static device scratch (allocation APIs are forbidden). Total 96 MB.
__device__ float  g_C[16384 * 512];            // 32 MB: [:,0:256]=proj (LN in place), [:,256:512]=residual
__device__ __half g_A[(size_t)SEG * 65536];    // 64 MB: chunk A_T[s][j][i] = A[s0+s,i,j], fp16

// ---------------------------------------------------------------------------
// K1: C[m,n] = sum_k X[m,k]*W[n,k]; W = rows of M (n<256) then W_res.
// 128x128x8 SGEMM, 8x8 microtile, packed f32x2 inner product, DOUBLE-BUFFERED
// smem with one sync per k-tile and register prefetch issued before compute.
// ---------------------------------------------------------------------------
__global__ __launch_bounds__(256) void k_proj(const float* __restrict__ X,
                                              const float* __restrict__ Mw,
                                              const float* __restrict__ Wr) {
    __shared__ float As[2][8][128];
    __shared__ float Bs[2][8][128];
    const int tid  = threadIdx.x;
    const int m0   = blockIdx.x * 128;
    const int n0   = blockIdx.y * 128;
    const int lrow = tid >> 1;
    const int lcol = (tid & 1) * 4;
    const int tx   = tid & 15;
    const int ty   = tid >> 4;

    const float* xrow = X + (size_t)(m0 + lrow) * 512;
    const float* wrow;
    {
        const int n = n0 + lrow;
        wrow = (n < 256) ? (Mw + (size_t)n * 512) : (Wr + (size_t)(n - 256) * 512);
    }

    u64 acc[8][4];
#pragma unroll
    for (int i = 0; i < 8; i++)
#pragma unroll
        for (int jp = 0; jp < 4; jp++) acc[i][jp] = 0ull;

    // Preload tile 0 and stage it into buffer 0.
    float4 av = *(const float4*)(xrow + lcol);
    float4 bv = *(const float4*)(wrow + lcol);
    As[0][lcol + 0][lrow] = av.x; As[0][lcol + 1][lrow] = av.y;
    As[0][lcol + 2][lrow] = av.z; As[0][lcol + 3][lrow] = av.w;
    Bs[0][lcol + 0][lrow] = bv.x; Bs[0][lcol + 1][lrow] = bv.y;
    Bs[0][lcol + 2][lrow] = bv.z; Bs[0][lcol + 3][lrow] = bv.w;

    int buf = 0;
    for (int k0 = 0; k0 < 512; k0 += 8) {
        __syncthreads();                      // orders prior STS (this buf) + prior compute (other buf)
        if (k0 + 8 < 512) {                   // prefetch next tile into registers (hides LDG latency)
            av = *(const float4*)(xrow + k0 + 8 + lcol);
            bv = *(const float4*)(wrow + k0 + 8 + lcol);
        }
#pragma unroll
        for (int k = 0; k < 8; k++) {
            u64 ap[8], bp[4];
            const u64* bs2 = (const u64*)&Bs[buf][k][tx * 8];   // 4 packed j-pairs
#pragma unroll
            for (int jp = 0; jp < 4; jp++) bp[jp] = bs2[jp];
#pragma unroll
            for (int i = 0; i < 8; i++) {
                const float a = As[buf][k][ty * 8 + i];
                ap[i] = pack2(a, a);
            }
#pragma unroll
            for (int i = 0; i < 8; i++)
#pragma unroll
                for (int jp = 0; jp < 4; jp++)
                    acc[i][jp] = fma2(ap[i], bp[jp], acc[i][jp]);
        }
        if (k0 + 8 < 512) {                   // stage prefetched tile into the other buffer
            const int nb = buf ^ 1;
            As[nb][lcol + 0][lrow] = av.x; As[nb][lcol + 1][lrow] = av.y;
            As[nb][lcol + 2][lrow] = av.z; As[nb][lcol + 3][lrow] = av.w;
            Bs[nb][lcol + 0][lrow] = bv.x; Bs[nb][lcol + 1][lrow] = bv.y;
            Bs[nb][lcol + 2][lrow] = bv.z; Bs[nb][lcol + 3][lrow] = bv.w;
        }
        buf ^= 1;
    }

#pragma unroll
    for (int i = 0; i < 8; i++) {
        u64* crow = (u64*)(g_C + (size_t)(m0 + ty * 8 + i) * 512 + n0 + tx * 8);
#pragma unroll
        for (int jp = 0; jp < 4; jp++) crow[jp] = acc[i][jp];
    }
}

// ---------------------------------------------------------------------------
// K2: LayerNorm over 256 of C[:,0:256], IN PLACE. Warp per row, 8 rows/block.
// ---------------------------------------------------------------------------
__global__ void k_ln(const float* __restrict__ sc, const float* __restrict__ bi) {
    const int row  = blockIdx.x * 8 + threadIdx.y;
    const int lane = threadIdx.x;
    float* h = g_C + (size_t)row * 512;
    float v[8];
    float s = 0.f;
#pragma unroll
    for (int k = 0; k < 8; k++) { v[k] = h[lane + 32 * k]; s += v[k]; }
#pragma unroll
    for (int o = 16; o > 0; o >>= 1) s += __shfl_xor_sync(0xffffffffu, s, o);
    const float mu = s * (1.f / 256.f);
    float q = 0.f;
#pragma unroll
    for (int k = 0; k < 8; k++) { const float d = v[k] - mu; q = fmaf(d, d, q); }
#pragma unroll
    for (int o = 16; o > 0; o >>= 1) q += __shfl_xor_sync(0xffffffffu, q, o);
    const float inv = rsqrtf(q * (1.f / 256.f) + 1e-5f);
#pragma unroll
    for (int k = 0; k < 8; k++) {
        const int c = lane + 32 * k;
        h[c] = (v[k] - mu) * inv * sc[c] + bi[c];
    }
}

// ---------------------------------------------------------------------------
// K3: fill g_A[(s-segBase)][j][i] = A[s,i,j] = sum_g P[i,j,g]*cos(2*pi*pos_s/T)
// via the exact "magic circle" oscillator (x<-x+eps*y; y<-y-eps*x,
// eps=2*sin(pi/T) => y_n = cos(n*theta) exactly in real arithmetic).
// P folded into the amplitude; per-step dot = 3 packed adds. Seeded by exact
// integer phase reduction + cospif/sinpif. SUBSEG=256 halves reseed overhead
// (drift ~1e-6, invisible under the fp16-A error floor).
// ---------------------------------------------------------------------------
__global__ __launch_bounds__(256) void k_genA(const float* __restrict__ P,
                                              const float* __restrict__ per,
                                              const int*   __restrict__ pos,
                                              int segBase) {
    const int i    = threadIdx.x;
    const int j    = blockIdx.x;
    const int sub  = blockIdx.y;               // 0..1
    const int s0   = segBase + sub * SUBSEG;
    const int base = (i * 256 + j) * 8;
    const int p0   = pos[s0];

    float ep[8], xo[8], yo[8];
#pragma unroll
    for (int g = 0; g < 8; g++) {
        const float pw = P[base + g];
        const int   Ti = (int)(per[base + g] + 0.5f);   // periods are exact integers
        const float Tf = (float)Ti;
        ep[g] = 2.f * sinpif(1.f / Tf);
        const int r = p0 % Ti;                           // exact phase reduction
        yo[g] = pw * cospif((float)(2 * r) / Tf);        // pw*cos(p0*theta)
        xo[g] = pw * sinpif((float)(2 * r - 1) / Tf);    // pw*sin((p0-1/2)*theta)
    }

    u64 ep2[4], nep2[4], x2[4], y2[4];
#pragma unroll
    for (int k = 0; k < 4; k++) {
        ep2[k]  = pack2(ep[2 * k], ep[2 * k + 1]);
        nep2[k] = pack2(-ep[2 * k], -ep[2 * k + 1]);
        x2[k]   = pack2(xo[2 * k], xo[2 * k + 1]);
        y2[k]   = pack2(yo[2 * k], yo[2 * k + 1]);
    }

    __half* outp = g_A + (size_t)(sub * SUBSEG) * 65536 + j * 256 + i;
#pragma unroll 2
    for (int s = 0; s < SUBSEG; s++) {
        const u64 s01 = add2(y2[0], y2[1]);
        const u64 s23 = add2(y2[2], y2[3]);
        const float2 f = unpack2(add2(s01, s23));
        *outp = __float2half_rn(f.x + f.y);
        outp += 65536;
#pragma unroll
        for (int k = 0; k < 4; k++) x2[k] = fma2(ep2[k], y2[k], x2[k]);   // old y
#pragma unroll
        for (int k = 0; k < 4; k++) y2[k] = fma2(nep2[k], x2[k], y2[k]);  // new x
    }
}

// ---------------------------------------------------------------------------
// K4: out[b,s,i] = sum_j t[b,s,j]*A[s,i,j] + residual[b,s,i].
// EXACT R10 structure (measured 36.3us/launch, best total 570us):
// block per s, 512 threads = (bh 0..1, jq 0..3, i4 0..63). Per j:
// 1 LDG.64 + 4 broadcast LDS.64 + 8 FFMA2, 8 packed accumulators, no reg cap.
// ---------------------------------------------------------------------------
__global__ __launch_bounds__(512) void k_contract(float* __restrict__ out,
                                                  int segBase) {
    __shared__ u64 t2[8][256];              // (t,t) duplicated pairs
    __shared__ u64 red[3][2][4][2][64];     // [jq-1][bh][b][i-pair][i4]
    const int sl  = blockIdx.x;
    const int s   = segBase + sl;
    const int tid = threadIdx.x;
    const int i4  = tid & 63;               // quad of 4 consecutive i
    const int jq  = (tid >> 6) & 3;         // 0..3
    const int bh  = tid >> 8;               // 0..1 (batch half)

    for (int v = tid; v < 2048; v += 512) {
        const int b = v >> 8, c = v & 255;
        const float t = g_C[((size_t)b * S_LEN + s) * 512 + c];
        t2[b][c] = pack2(t, t);
    }
    __syncthreads();

    u64 acc[4][2];
#pragma unroll
    for (int b = 0; b < 4; b++) { acc[b][0] = 0ull; acc[b][1] = 0ull; }

    // A rows: 256 halves = 64 uint2 per row; this thread reads uint2 #i4.
    const uint2* Ab = (const uint2*)(g_A + (size_t)sl * 65536) + i4;
    const int j0 = jq * 64;
    const int b0 = bh * 4;

#pragma unroll 4
    for (int j = j0; j < j0 + 64; j++) {
        const uint2 raw = Ab[(size_t)j * 64];
        const float2 f01 = __half22float2(*(const __half2*)&raw.x);
        const float2 f23 = __half22float2(*(const __half2*)&raw.y);
        const u64 a01 = pack2(f01.x, f01.y);
        const u64 a23 = pack2(f23.x, f23.y);
#pragma unroll
        for (int b = 0; b < 4; b++) {
            const u64 t = t2[b0 + b][j];
            acc[b][0] = fma2(t, a01, acc[b][0]);
            acc[b][1] = fma2(t, a23, acc[b][1]);
        }
    }

    if (jq > 0) {
#pragma unroll
        for (int b = 0; b < 4; b++) {
            red[jq - 1][bh][b][0][i4] = acc[b][0];
            red[jq - 1][bh][b][1][i4] = acc[b][1];
        }
    }
    __syncthreads();

    if (jq == 0) {
#pragma unroll
        for (int b = 0; b < 4; b++) {
            const int bg = b0 + b;
            const u64 r0 = add2(add2(acc[b][0], red[0][bh][b][0][i4]),
                                add2(red[1][bh][b][0][i4], red[2][bh][b][0][i4]));
            const u64 r1 = add2(add2(acc[b][1], red[0][bh][b][1][i4]),
                                add2(red[1][bh][b][1][i4], red[2][bh][b][1][i4]));
            const float2 s0 = unpack2(r0), s1 = unpack2(r1);
            const float4 r = *(const float4*)&g_C[((size_t)bg * S_LEN + s) * 512 + 256 + i4 * 4];
            const float4 o = make_float4(s0.x + r.x, s0.y + r.y, s1.x + r.z, s1.y + r.w);
            *(float4*)&out[((size_t)bg * S_LEN + s) * 256 + i4 * 4] = o;
        }
    }
}

// ---------------------------------------------------------------------------
// Inputs (metadata order): x, M, P, W_res, ln_scale, ln_bias, periods, positions
// ---------------------------------------------------------------------------
extern "C" void kernel_launch(void* const* d_in, const int* in_sizes, int n_in,
                              void* d_out, int out_size) {
    const float* x   = (const float*)d_in[0];
    const float* M   = (const float*)d_in[1];
    const float* P   = (const float*)d_in[2];
    const float* Wr  = (const float*)d_in[3];
    const float* lns = (const float*)d_in[4];
    const float* lnb = (const float*)d_in[5];
    const float* per = (const float*)d_in[6];
    const int*   pos = (const int*)d_in[7];
    float* out = (float*)d_out;
    (void)in_sizes; (void)n_in; (void)out_size;

    k_proj<<<dim3(128, 4), 256>>>(x, M, Wr);
    k_ln<<<2048, dim3(32, 8)>>>(lns, lnb);

    for (int seg = 0; seg < S_LEN / SEG; seg++) {
        const int segBase = seg * SEG;
        k_genA<<<dim3(256, SEG / SUBSEG), 256>>>(P, per, pos, segBase);
        k_contract<<<SEG, 512>>>(out, segBase);
    }
}